// round 13
// baseline (speedup 1.0000x reference)
#include <cuda_runtime.h>
#include <cuda_bf16.h>

#define N_NODES 100000
#define N_EDGES 3200000
#define IN_F    128
#define HID     3
#define OUT_F   4

// Fused kernel 1: every 5th block does degree atomics, the rest do the GEMV.
#define FUSED_BLOCKS 15625

// k_edge: single-wave persistent grid (148 SMs x 8 resident blocks)
#define EDGE_BLOCKS  1184
#define EDGE_THREADS 256
#define EDGE_TOTAL   (EDGE_BLOCKS * EDGE_THREADS)

// Scratch (device globals — zero-initialized at load; g_deg kept zero at entry
// by k_scale resetting it every call)
__device__ float  g_deg[N_NODES];
__device__ float  g_dinv[N_NODES];
__device__ float4 g_sxw4[N_NODES];
__device__ float4 g_T4[N_NODES];

// ---------------------------------------------------------------------------
// 1) Fused deg + GEMV, role-interleaved by blockIdx % 5 so every scheduling
//    wave carries both atomic-bound (LSU/LTS) and DRAM-bound work.
//    PDL: input loads pre-sync; g_* writes post-sync.
__global__ void k_deg_gemv(const int* __restrict__ col,
                           const float* __restrict__ x,
                           const float* __restrict__ W) {
    int q = blockIdx.x / 5;
    int r = blockIdx.x % 5;
    int tid = threadIdx.x;

    if (r == 0) {
        // ---- degree role (block q of 3125): 4 edges/thread, int4 col load
        int e = (q * blockDim.x + tid) * 4;
        int4 c4 = make_int4(-1, -1, -1, -1);
        if (e + 3 < N_EDGES)                  // N_EDGES % 4 == 0 -> exact
            c4 = *reinterpret_cast<const int4*>(col + e);
        cudaGridDependencySynchronize();
        if ((unsigned)c4.x < N_NODES) atomicAdd(&g_deg[c4.x], 1.0f);
        if ((unsigned)c4.y < N_NODES) atomicAdd(&g_deg[c4.y], 1.0f);
        if ((unsigned)c4.z < N_NODES) atomicAdd(&g_deg[c4.z], 1.0f);
        if ((unsigned)c4.w < N_NODES) atomicAdd(&g_deg[c4.w], 1.0f);
        cudaTriggerProgrammaticLaunchCompletion();
        return;
    }

    // ---- GEMV role: warp-per-node, xw = x[node] @ W (128 -> 3), unscaled
    __shared__ float sW[IN_F * HID];
    for (int i = tid; i < IN_F * HID; i += blockDim.x) sW[i] = W[i];
    __syncthreads();

    int g = q * 4 + (r - 1);
    int node = g * 8 + (tid >> 5);
    int lane = tid & 31;

    float a0 = 0.f, a1 = 0.f, a2 = 0.f;
    if (node < N_NODES) {
        const float4 xv = *reinterpret_cast<const float4*>(
            x + (size_t)node * IN_F + lane * 4);
        int k0 = lane * 4;
        const float* w0 = &sW[(k0 + 0) * HID];
        const float* w1 = &sW[(k0 + 1) * HID];
        const float* w2 = &sW[(k0 + 2) * HID];
        const float* w3 = &sW[(k0 + 3) * HID];

        a0 = xv.x * w0[0] + xv.y * w1[0] + xv.z * w2[0] + xv.w * w3[0];
        a1 = xv.x * w0[1] + xv.y * w1[1] + xv.z * w2[1] + xv.w * w3[1];
        a2 = xv.x * w0[2] + xv.y * w1[2] + xv.z * w2[2] + xv.w * w3[2];

        #pragma unroll
        for (int off = 16; off > 0; off >>= 1) {
            a0 += __shfl_down_sync(0xffffffffu, a0, off);
            a1 += __shfl_down_sync(0xffffffffu, a1, off);
            a2 += __shfl_down_sync(0xffffffffu, a2, off);
        }
    }

    cudaGridDependencySynchronize();
    if (node < N_NODES && lane == 0) {
        g_sxw4[node] = make_float4(a0, a1, a2, 0.0f);
    }
    cudaTriggerProgrammaticLaunchCompletion();
}

// ---------------------------------------------------------------------------
// 2) Per node (2 nodes/thread, 196 blocks for faster ramp): dinv =
//    rsqrt(deg+1); scale sxw4; seed T4 with self-loop term; reset g_deg.
__global__ void k_scale() {
    cudaGridDependencySynchronize();   // needs deg + sxw4 complete
    int t = blockIdx.x * blockDim.x + threadIdx.x;
    int i = t * 2;
    if (i + 1 < N_NODES) {             // N_NODES even -> exact pairs
        float2 d2 = *reinterpret_cast<float2*>(&g_deg[i]);
        float2 dv;
        dv.x = rsqrtf(d2.x + 1.0f);
        dv.y = rsqrtf(d2.y + 1.0f);
        *reinterpret_cast<float2*>(&g_deg[i])  = make_float2(0.f, 0.f);
        *reinterpret_cast<float2*>(&g_dinv[i]) = dv;

        float4 s0 = g_sxw4[i + 0];
        float4 s1 = g_sxw4[i + 1];
        s0.x *= dv.x; s0.y *= dv.x; s0.z *= dv.x;
        s1.x *= dv.y; s1.y *= dv.y; s1.z *= dv.y;
        g_sxw4[i + 0] = s0;  g_T4[i + 0] = s0;
        g_sxw4[i + 1] = s1;  g_T4[i + 1] = s1;
    }
    cudaTriggerProgrammaticLaunchCompletion();
}

// ---------------------------------------------------------------------------
// 3) Edge scatter: single-wave grid-stride (1184 blocks), 4 edges per chunk.
//    Software-pipelined: next chunk's index loads issue BEFORE the current
//    chunk's REDs; gathers hoisted so 4 LDG.128 are outstanding together.
__global__ void __launch_bounds__(EDGE_THREADS, 8)
k_edge(const int* __restrict__ ei) {
    const unsigned gtid = blockIdx.x * EDGE_THREADS + threadIdx.x;
    const unsigned NCHUNK = N_EDGES / 4;       // 800,000 exact

    // First chunk's indices pre-sync (pure input).
    int4 r4 = make_int4(-1, -1, -1, -1);
    int4 c4 = make_int4(-1, -1, -1, -1);
    if (gtid < NCHUNK) {
        r4 = *reinterpret_cast<const int4*>(ei + gtid * 4);
        c4 = *reinterpret_cast<const int4*>(ei + N_EDGES + gtid * 4);
    }
    cudaGridDependencySynchronize();           // sxw4 / T4 ready

    unsigned c = gtid;
    while (c < NCHUNK) {
        // gathers for current chunk (4 independent LDG.128)
        float4 s0, s1, s2, s3;
        bool v0 = (unsigned)r4.x < N_NODES && (unsigned)c4.x < N_NODES;
        bool v1 = (unsigned)r4.y < N_NODES && (unsigned)c4.y < N_NODES;
        bool v2 = (unsigned)r4.z < N_NODES && (unsigned)c4.z < N_NODES;
        bool v3 = (unsigned)r4.w < N_NODES && (unsigned)c4.w < N_NODES;
        if (v0) s0 = g_sxw4[r4.x];
        if (v1) s1 = g_sxw4[r4.y];
        if (v2) s2 = g_sxw4[r4.z];
        if (v3) s3 = g_sxw4[r4.w];

        // prefetch next chunk's indices before issuing REDs
        unsigned cn = c + EDGE_TOTAL;
        int4 nr4 = make_int4(-1, -1, -1, -1);
        int4 nc4 = make_int4(-1, -1, -1, -1);
        if (cn < NCHUNK) {
            nr4 = *reinterpret_cast<const int4*>(ei + cn * 4);
            nc4 = *reinterpret_cast<const int4*>(ei + N_EDGES + cn * 4);
        }

        // fire-and-forget REDs
        if (v0) atomicAdd(&g_T4[c4.x], s0);
        if (v1) atomicAdd(&g_T4[c4.y], s1);
        if (v2) atomicAdd(&g_T4[c4.z], s2);
        if (v3) atomicAdd(&g_T4[c4.w], s3);

        c = cn; r4 = nr4; c4 = nc4;
    }
    cudaTriggerProgrammaticLaunchCompletion();
}

// ---------------------------------------------------------------------------
// 4) Epilogue, role-split over 2*N_NODES threads:
//    t < N:  compute h[t], store 3 floats;  t >= N: recompute h, store z float4.
__global__ void k_final(const float* __restrict__ b,
                        const float* __restrict__ Wout,
                        const float* __restrict__ bout,
                        float* __restrict__ out) {
    unsigned t = blockIdx.x * blockDim.x + threadIdx.x;
    bool zrole = (t >= N_NODES);
    unsigned i = zrole ? t - N_NODES : t;
    bool valid = (t < 2u * N_NODES);

    float b0 = __ldg(&b[0]), b1 = __ldg(&b[1]), b2 = __ldg(&b[2]);
    float w00 = 0, w01 = 0, w02 = 0, w03 = 0;
    float w10 = 0, w11 = 0, w12 = 0, w13 = 0;
    float w20 = 0, w21 = 0, w22 = 0, w23 = 0;
    float zb0 = 0, zb1 = 0, zb2 = 0, zb3 = 0;
    if (zrole) {
        w00 = __ldg(&Wout[0]);  w01 = __ldg(&Wout[1]);  w02 = __ldg(&Wout[2]);  w03 = __ldg(&Wout[3]);
        w10 = __ldg(&Wout[4]);  w11 = __ldg(&Wout[5]);  w12 = __ldg(&Wout[6]);  w13 = __ldg(&Wout[7]);
        w20 = __ldg(&Wout[8]);  w21 = __ldg(&Wout[9]);  w22 = __ldg(&Wout[10]); w23 = __ldg(&Wout[11]);
        zb0 = __ldg(&bout[0]);  zb1 = __ldg(&bout[1]);  zb2 = __ldg(&bout[2]);  zb3 = __ldg(&bout[3]);
    }

    cudaGridDependencySynchronize();   // T4 aggregation complete
    if (!valid) return;

    float dinv = g_dinv[i];
    float4 tv  = g_T4[i];
    float h0 = fmaxf(tv.x * dinv + b0, 0.0f);
    float h1 = fmaxf(tv.y * dinv + b1, 0.0f);
    float h2 = fmaxf(tv.z * dinv + b2, 0.0f);

    if (!zrole) {
        unsigned base = i * HID;
        out[base + 0] = h0;
        out[base + 1] = h1;
        out[base + 2] = h2;
    } else {
        float4 z;
        z.x = h0 * w00 + h1 * w10 + h2 * w20 + zb0;
        z.y = h0 * w01 + h1 * w11 + h2 * w21 + zb1;
        z.z = h0 * w02 + h1 * w12 + h2 * w22 + zb2;
        z.w = h0 * w03 + h1 * w13 + h2 * w23 + zb3;
        *reinterpret_cast<float4*>(out + (size_t)N_NODES * HID + (size_t)i * OUT_F) = z;
    }
}

// ---------------------------------------------------------------------------
static inline void launch_pdl(void* fn, dim3 grid, dim3 block, void** args) {
    cudaLaunchConfig_t cfg = {};
    cfg.gridDim = grid;
    cfg.blockDim = block;
    cfg.dynamicSmemBytes = 0;
    cfg.stream = 0;   // capturing (default) stream
    cudaLaunchAttribute attr[1];
    attr[0].id = cudaLaunchAttributeProgrammaticStreamSerialization;
    attr[0].val.programmaticStreamSerializationAllowed = 1;
    cfg.attrs = attr;
    cfg.numAttrs = 1;
    cudaLaunchKernelExC(&cfg, fn, args);
}

extern "C" void kernel_launch(void* const* d_in, const int* in_sizes, int n_in,
                              void* d_out, int out_size) {
    // Bind inputs by element count (robust to ordering):
    // x=12,800,000  edge_index=6,400,000  W=384  b=3  Wout=12  bout=4
    const float* x    = nullptr;
    const int*   ei   = nullptr;
    const float* W    = nullptr;
    const float* b    = nullptr;
    const float* Wout = nullptr;
    const float* bout = nullptr;
    for (int i = 0; i < n_in; i++) {
        switch (in_sizes[i]) {
            case 12800000: x    = (const float*)d_in[i]; break;
            case 6400000:  ei   = (const int*)  d_in[i]; break;
            case 384:      W    = (const float*)d_in[i]; break;
            case 3:        b    = (const float*)d_in[i]; break;
            case 12:       Wout = (const float*)d_in[i]; break;
            case 4:        bout = (const float*)d_in[i]; break;
            default: break;
        }
    }

    float* out = (float*)d_out;
    const int T = 256;
    const int* col = ei + N_EDGES;

    {
        void* args[] = { (void*)&col, (void*)&x, (void*)&W };
        launch_pdl((void*)k_deg_gemv, dim3(FUSED_BLOCKS), dim3(T), args);
    }
    {
        void* args[] = { };
        cudaLaunchConfig_t cfg = {};
        cfg.gridDim = dim3((N_NODES / 2 + T - 1) / T);
        cfg.blockDim = dim3(T);
        cfg.stream = 0;
        cudaLaunchAttribute attr[1];
        attr[0].id = cudaLaunchAttributeProgrammaticStreamSerialization;
        attr[0].val.programmaticStreamSerializationAllowed = 1;
        cfg.attrs = attr;
        cfg.numAttrs = 1;
        cudaLaunchKernelExC(&cfg, (void*)k_scale, args);
    }
    {
        void* args[] = { (void*)&ei };
        launch_pdl((void*)k_edge, dim3(EDGE_BLOCKS), dim3(EDGE_THREADS), args);
    }
    {
        void* args[] = { (void*)&b, (void*)&Wout, (void*)&bout, (void*)&out };
        launch_pdl((void*)k_final, dim3((2 * N_NODES + T - 1) / T), dim3(T), args);
    }
}

// round 14
// speedup vs baseline: 1.1251x; 1.1251x over previous
#include <cuda_runtime.h>
#include <cuda_bf16.h>

#define N_NODES 100000
#define N_EDGES 3200000
#define IN_F    128
#define HID     3
#define OUT_F   4

// Fused kernel 1: every 5th block does degree atomics, the rest do the GEMV.
#define FUSED_BLOCKS 15625

// k_edge: single-wave persistent grid (148 SMs x 8 resident blocks)
#define EDGE_BLOCKS  1184
#define EDGE_THREADS 256
#define EDGE_TOTAL   (EDGE_BLOCKS * EDGE_THREADS)

// Scratch (device globals — zero-initialized at load; g_deg kept zero at entry
// by k_scale resetting it every call)
__device__ float  g_deg[N_NODES];
__device__ float  g_dinv[N_NODES];
__device__ float4 g_sxw4[N_NODES];
__device__ float4 g_T4[N_NODES];

// ---------------------------------------------------------------------------
// 1) Fused deg + GEMV, role-interleaved by blockIdx % 5 so every scheduling
//    wave carries both atomic-bound (LSU/LTS) and DRAM-bound work.
//    PDL: input loads pre-sync; g_* writes post-sync.
__global__ void k_deg_gemv(const int* __restrict__ col,
                           const float* __restrict__ x,
                           const float* __restrict__ W) {
    int q = blockIdx.x / 5;
    int r = blockIdx.x % 5;
    int tid = threadIdx.x;

    if (r == 0) {
        // ---- degree role (block q of 3125): 4 edges/thread, int4 col load
        int e = (q * blockDim.x + tid) * 4;
        int4 c4 = make_int4(-1, -1, -1, -1);
        if (e + 3 < N_EDGES)                  // N_EDGES % 4 == 0 -> exact
            c4 = *reinterpret_cast<const int4*>(col + e);
        cudaGridDependencySynchronize();
        if ((unsigned)c4.x < N_NODES) atomicAdd(&g_deg[c4.x], 1.0f);
        if ((unsigned)c4.y < N_NODES) atomicAdd(&g_deg[c4.y], 1.0f);
        if ((unsigned)c4.z < N_NODES) atomicAdd(&g_deg[c4.z], 1.0f);
        if ((unsigned)c4.w < N_NODES) atomicAdd(&g_deg[c4.w], 1.0f);
        cudaTriggerProgrammaticLaunchCompletion();
        return;
    }

    // ---- GEMV role: warp-per-node, xw = x[node] @ W (128 -> 3), unscaled
    __shared__ float sW[IN_F * HID];
    for (int i = tid; i < IN_F * HID; i += blockDim.x) sW[i] = W[i];
    __syncthreads();

    int g = q * 4 + (r - 1);
    int node = g * 8 + (tid >> 5);
    int lane = tid & 31;

    float a0 = 0.f, a1 = 0.f, a2 = 0.f;
    if (node < N_NODES) {
        const float4 xv = *reinterpret_cast<const float4*>(
            x + (size_t)node * IN_F + lane * 4);
        int k0 = lane * 4;
        const float* w0 = &sW[(k0 + 0) * HID];
        const float* w1 = &sW[(k0 + 1) * HID];
        const float* w2 = &sW[(k0 + 2) * HID];
        const float* w3 = &sW[(k0 + 3) * HID];

        a0 = xv.x * w0[0] + xv.y * w1[0] + xv.z * w2[0] + xv.w * w3[0];
        a1 = xv.x * w0[1] + xv.y * w1[1] + xv.z * w2[1] + xv.w * w3[1];
        a2 = xv.x * w0[2] + xv.y * w1[2] + xv.z * w2[2] + xv.w * w3[2];

        #pragma unroll
        for (int off = 16; off > 0; off >>= 1) {
            a0 += __shfl_down_sync(0xffffffffu, a0, off);
            a1 += __shfl_down_sync(0xffffffffu, a1, off);
            a2 += __shfl_down_sync(0xffffffffu, a2, off);
        }
    }

    cudaGridDependencySynchronize();
    if (node < N_NODES && lane == 0) {
        g_sxw4[node] = make_float4(a0, a1, a2, 0.0f);
    }
    cudaTriggerProgrammaticLaunchCompletion();
}

// ---------------------------------------------------------------------------
// 2) Per node (4 nodes/thread, vectorized): dinv = rsqrt(deg+1); scale sxw4;
//    seed T4 with self-loop term; reset g_deg for next replay.
__global__ void k_scale() {
    cudaGridDependencySynchronize();   // needs deg + sxw4 complete
    int t = blockIdx.x * blockDim.x + threadIdx.x;
    int i = t * 4;
    if (i + 3 < N_NODES) {             // N_NODES % 4 == 0 -> exact
        float4 d4 = *reinterpret_cast<float4*>(&g_deg[i]);
        float4 dv;
        dv.x = rsqrtf(d4.x + 1.0f);
        dv.y = rsqrtf(d4.y + 1.0f);
        dv.z = rsqrtf(d4.z + 1.0f);
        dv.w = rsqrtf(d4.w + 1.0f);
        *reinterpret_cast<float4*>(&g_deg[i])  = make_float4(0.f, 0.f, 0.f, 0.f);
        *reinterpret_cast<float4*>(&g_dinv[i]) = dv;

        float4 s0 = g_sxw4[i + 0];
        float4 s1 = g_sxw4[i + 1];
        float4 s2 = g_sxw4[i + 2];
        float4 s3 = g_sxw4[i + 3];
        s0.x *= dv.x; s0.y *= dv.x; s0.z *= dv.x;
        s1.x *= dv.y; s1.y *= dv.y; s1.z *= dv.y;
        s2.x *= dv.z; s2.y *= dv.z; s2.z *= dv.z;
        s3.x *= dv.w; s3.y *= dv.w; s3.z *= dv.w;
        g_sxw4[i + 0] = s0;  g_T4[i + 0] = s0;
        g_sxw4[i + 1] = s1;  g_T4[i + 1] = s1;
        g_sxw4[i + 2] = s2;  g_T4[i + 2] = s2;
        g_sxw4[i + 3] = s3;  g_T4[i + 3] = s3;
    }
    cudaTriggerProgrammaticLaunchCompletion();
}

// ---------------------------------------------------------------------------
// 3) Edge scatter: single-wave grid-stride (1184 blocks), 4 edges per chunk,
//    int4 index loads, LDG.128 gather + RED.128 per edge. ~2.64 chunks/thread
//    give extra MLP; no wave transitions. Straight-line loop body — ptxas
//    front-batches the loads itself; manual pipelining regressed (round 13).
__global__ void __launch_bounds__(EDGE_THREADS, 8)
k_edge(const int* __restrict__ ei) {
    const unsigned gtid = blockIdx.x * EDGE_THREADS + threadIdx.x;
    const unsigned NCHUNK = N_EDGES / 4;       // 800,000 exact

    // First chunk's indices pre-sync (pure input).
    int4 r4 = make_int4(-1, -1, -1, -1);
    int4 c4 = make_int4(-1, -1, -1, -1);
    if (gtid < NCHUNK) {
        r4 = *reinterpret_cast<const int4*>(ei + gtid * 4);
        c4 = *reinterpret_cast<const int4*>(ei + N_EDGES + gtid * 4);
    }
    cudaGridDependencySynchronize();           // sxw4 / T4 ready

    for (unsigned c = gtid; c < NCHUNK; ) {
        // issue gathers + REDs for current chunk
        if ((unsigned)r4.x < N_NODES && (unsigned)c4.x < N_NODES)
            atomicAdd(&g_T4[c4.x], g_sxw4[r4.x]);
        if ((unsigned)r4.y < N_NODES && (unsigned)c4.y < N_NODES)
            atomicAdd(&g_T4[c4.y], g_sxw4[r4.y]);
        if ((unsigned)r4.z < N_NODES && (unsigned)c4.z < N_NODES)
            atomicAdd(&g_T4[c4.z], g_sxw4[r4.z]);
        if ((unsigned)r4.w < N_NODES && (unsigned)c4.w < N_NODES)
            atomicAdd(&g_T4[c4.w], g_sxw4[r4.w]);
        // fetch next chunk's indices (overlaps the REDs above)
        c += EDGE_TOTAL;
        if (c < NCHUNK) {
            r4 = *reinterpret_cast<const int4*>(ei + c * 4);
            c4 = *reinterpret_cast<const int4*>(ei + N_EDGES + c * 4);
        } else break;
    }
    cudaTriggerProgrammaticLaunchCompletion();
}

// ---------------------------------------------------------------------------
// 4) Epilogue, role-split over 2*N_NODES threads:
//    t < N:  compute h[t], store 3 floats;  t >= N: recompute h, store z float4.
__global__ void k_final(const float* __restrict__ b,
                        const float* __restrict__ Wout,
                        const float* __restrict__ bout,
                        float* __restrict__ out) {
    unsigned t = blockIdx.x * blockDim.x + threadIdx.x;
    bool zrole = (t >= N_NODES);
    unsigned i = zrole ? t - N_NODES : t;
    bool valid = (t < 2u * N_NODES);

    float b0 = __ldg(&b[0]), b1 = __ldg(&b[1]), b2 = __ldg(&b[2]);
    float w00 = 0, w01 = 0, w02 = 0, w03 = 0;
    float w10 = 0, w11 = 0, w12 = 0, w13 = 0;
    float w20 = 0, w21 = 0, w22 = 0, w23 = 0;
    float zb0 = 0, zb1 = 0, zb2 = 0, zb3 = 0;
    if (zrole) {
        w00 = __ldg(&Wout[0]);  w01 = __ldg(&Wout[1]);  w02 = __ldg(&Wout[2]);  w03 = __ldg(&Wout[3]);
        w10 = __ldg(&Wout[4]);  w11 = __ldg(&Wout[5]);  w12 = __ldg(&Wout[6]);  w13 = __ldg(&Wout[7]);
        w20 = __ldg(&Wout[8]);  w21 = __ldg(&Wout[9]);  w22 = __ldg(&Wout[10]); w23 = __ldg(&Wout[11]);
        zb0 = __ldg(&bout[0]);  zb1 = __ldg(&bout[1]);  zb2 = __ldg(&bout[2]);  zb3 = __ldg(&bout[3]);
    }

    cudaGridDependencySynchronize();   // T4 aggregation complete
    if (!valid) return;

    float dinv = g_dinv[i];
    float4 tv  = g_T4[i];
    float h0 = fmaxf(tv.x * dinv + b0, 0.0f);
    float h1 = fmaxf(tv.y * dinv + b1, 0.0f);
    float h2 = fmaxf(tv.z * dinv + b2, 0.0f);

    if (!zrole) {
        unsigned base = i * HID;
        out[base + 0] = h0;
        out[base + 1] = h1;
        out[base + 2] = h2;
    } else {
        float4 z;
        z.x = h0 * w00 + h1 * w10 + h2 * w20 + zb0;
        z.y = h0 * w01 + h1 * w11 + h2 * w21 + zb1;
        z.z = h0 * w02 + h1 * w12 + h2 * w22 + zb2;
        z.w = h0 * w03 + h1 * w13 + h2 * w23 + zb3;
        *reinterpret_cast<float4*>(out + (size_t)N_NODES * HID + (size_t)i * OUT_F) = z;
    }
}

// ---------------------------------------------------------------------------
static inline void launch_pdl(void* fn, dim3 grid, dim3 block, void** args) {
    cudaLaunchConfig_t cfg = {};
    cfg.gridDim = grid;
    cfg.blockDim = block;
    cfg.dynamicSmemBytes = 0;
    cfg.stream = 0;   // capturing (default) stream
    cudaLaunchAttribute attr[1];
    attr[0].id = cudaLaunchAttributeProgrammaticStreamSerialization;
    attr[0].val.programmaticStreamSerializationAllowed = 1;
    cfg.attrs = attr;
    cfg.numAttrs = 1;
    cudaLaunchKernelExC(&cfg, fn, args);
}

extern "C" void kernel_launch(void* const* d_in, const int* in_sizes, int n_in,
                              void* d_out, int out_size) {
    // Bind inputs by element count (robust to ordering):
    // x=12,800,000  edge_index=6,400,000  W=384  b=3  Wout=12  bout=4
    const float* x    = nullptr;
    const int*   ei   = nullptr;
    const float* W    = nullptr;
    const float* b    = nullptr;
    const float* Wout = nullptr;
    const float* bout = nullptr;
    for (int i = 0; i < n_in; i++) {
        switch (in_sizes[i]) {
            case 12800000: x    = (const float*)d_in[i]; break;
            case 6400000:  ei   = (const int*)  d_in[i]; break;
            case 384:      W    = (const float*)d_in[i]; break;
            case 3:        b    = (const float*)d_in[i]; break;
            case 12:       Wout = (const float*)d_in[i]; break;
            case 4:        bout = (const float*)d_in[i]; break;
            default: break;
        }
    }

    float* out = (float*)d_out;
    const int T = 256;
    const int* col = ei + N_EDGES;

    {
        void* args[] = { (void*)&col, (void*)&x, (void*)&W };
        launch_pdl((void*)k_deg_gemv, dim3(FUSED_BLOCKS), dim3(T), args);
    }
    {
        void* args[] = { };
        cudaLaunchConfig_t cfg = {};
        cfg.gridDim = dim3((N_NODES / 4 + T - 1) / T);
        cfg.blockDim = dim3(T);
        cfg.stream = 0;
        cudaLaunchAttribute attr[1];
        attr[0].id = cudaLaunchAttributeProgrammaticStreamSerialization;
        attr[0].val.programmaticStreamSerializationAllowed = 1;
        cfg.attrs = attr;
        cfg.numAttrs = 1;
        cudaLaunchKernelExC(&cfg, (void*)k_scale, args);
    }
    {
        void* args[] = { (void*)&ei };
        launch_pdl((void*)k_edge, dim3(EDGE_BLOCKS), dim3(EDGE_THREADS), args);
    }
    {
        void* args[] = { (void*)&b, (void*)&Wout, (void*)&bout, (void*)&out };
        launch_pdl((void*)k_final, dim3((2 * N_NODES + T - 1) / T), dim3(T), args);
    }
}

// round 15
// speedup vs baseline: 1.1341x; 1.0080x over previous
#include <cuda_runtime.h>
#include <cuda_bf16.h>

#define N_NODES 100000
#define N_EDGES 3200000
#define IN_F    128
#define HID     3
#define OUT_F   4

// Fused kernel 1: every 5th block does degree atomics, the rest do the GEMV.
#define FUSED_BLOCKS 15625

// k_edge: single-wave persistent grid (148 SMs x 8 resident blocks)
#define EDGE_BLOCKS  1184
#define EDGE_THREADS 256
#define EDGE_TOTAL   (EDGE_BLOCKS * EDGE_THREADS)

// Scratch (device globals — zero-initialized at load; g_deg kept zero at entry
// by k_scale resetting it every call)
__device__ float  g_deg[N_NODES];
__device__ float  g_dinv[N_NODES];
__device__ float4 g_sxw4[N_NODES];
__device__ float4 g_T4[N_NODES];

// ---------------------------------------------------------------------------
// 1) Fused deg + GEMV, role-interleaved by blockIdx % 5 so every scheduling
//    wave carries both atomic-bound (LSU/LTS) and DRAM-bound work.
//    PDL: input loads pre-sync; g_* writes post-sync.
__global__ void k_deg_gemv(const int* __restrict__ col,
                           const float* __restrict__ x,
                           const float* __restrict__ W) {
    int q = blockIdx.x / 5;
    int r = blockIdx.x % 5;
    int tid = threadIdx.x;

    if (r == 0) {
        // ---- degree role (block q of 3125): 4 edges/thread, int4 col load
        int e = (q * blockDim.x + tid) * 4;
        int4 c4 = make_int4(-1, -1, -1, -1);
        if (e + 3 < N_EDGES)                  // N_EDGES % 4 == 0 -> exact
            c4 = *reinterpret_cast<const int4*>(col + e);
        cudaGridDependencySynchronize();
        if ((unsigned)c4.x < N_NODES) atomicAdd(&g_deg[c4.x], 1.0f);
        if ((unsigned)c4.y < N_NODES) atomicAdd(&g_deg[c4.y], 1.0f);
        if ((unsigned)c4.z < N_NODES) atomicAdd(&g_deg[c4.z], 1.0f);
        if ((unsigned)c4.w < N_NODES) atomicAdd(&g_deg[c4.w], 1.0f);
        cudaTriggerProgrammaticLaunchCompletion();
        return;
    }

    // ---- GEMV role: warp-per-node, xw = x[node] @ W (128 -> 3), unscaled
    __shared__ float sW[IN_F * HID];
    for (int i = tid; i < IN_F * HID; i += blockDim.x) sW[i] = W[i];
    __syncthreads();

    int g = q * 4 + (r - 1);
    int node = g * 8 + (tid >> 5);
    int lane = tid & 31;

    float a0 = 0.f, a1 = 0.f, a2 = 0.f;
    if (node < N_NODES) {
        const float4 xv = *reinterpret_cast<const float4*>(
            x + (size_t)node * IN_F + lane * 4);
        int k0 = lane * 4;
        const float* w0 = &sW[(k0 + 0) * HID];
        const float* w1 = &sW[(k0 + 1) * HID];
        const float* w2 = &sW[(k0 + 2) * HID];
        const float* w3 = &sW[(k0 + 3) * HID];

        a0 = xv.x * w0[0] + xv.y * w1[0] + xv.z * w2[0] + xv.w * w3[0];
        a1 = xv.x * w0[1] + xv.y * w1[1] + xv.z * w2[1] + xv.w * w3[1];
        a2 = xv.x * w0[2] + xv.y * w1[2] + xv.z * w2[2] + xv.w * w3[2];

        #pragma unroll
        for (int off = 16; off > 0; off >>= 1) {
            a0 += __shfl_down_sync(0xffffffffu, a0, off);
            a1 += __shfl_down_sync(0xffffffffu, a1, off);
            a2 += __shfl_down_sync(0xffffffffu, a2, off);
        }
    }

    cudaGridDependencySynchronize();
    if (node < N_NODES && lane == 0) {
        g_sxw4[node] = make_float4(a0, a1, a2, 0.0f);
    }
    cudaTriggerProgrammaticLaunchCompletion();
}

// ---------------------------------------------------------------------------
// 2) Per node (4 nodes/thread, vectorized): dinv = rsqrt(deg+1); scale sxw4;
//    seed T4 with self-loop term; reset g_deg for next replay.
__global__ void k_scale() {
    cudaGridDependencySynchronize();   // needs deg + sxw4 complete
    int t = blockIdx.x * blockDim.x + threadIdx.x;
    int i = t * 4;
    if (i + 3 < N_NODES) {             // N_NODES % 4 == 0 -> exact
        float4 d4 = *reinterpret_cast<float4*>(&g_deg[i]);
        float4 dv;
        dv.x = rsqrtf(d4.x + 1.0f);
        dv.y = rsqrtf(d4.y + 1.0f);
        dv.z = rsqrtf(d4.z + 1.0f);
        dv.w = rsqrtf(d4.w + 1.0f);
        *reinterpret_cast<float4*>(&g_deg[i])  = make_float4(0.f, 0.f, 0.f, 0.f);
        *reinterpret_cast<float4*>(&g_dinv[i]) = dv;

        float4 s0 = g_sxw4[i + 0];
        float4 s1 = g_sxw4[i + 1];
        float4 s2 = g_sxw4[i + 2];
        float4 s3 = g_sxw4[i + 3];
        s0.x *= dv.x; s0.y *= dv.x; s0.z *= dv.x;
        s1.x *= dv.y; s1.y *= dv.y; s1.z *= dv.y;
        s2.x *= dv.z; s2.y *= dv.z; s2.z *= dv.z;
        s3.x *= dv.w; s3.y *= dv.w; s3.z *= dv.w;
        g_sxw4[i + 0] = s0;  g_T4[i + 0] = s0;
        g_sxw4[i + 1] = s1;  g_T4[i + 1] = s1;
        g_sxw4[i + 2] = s2;  g_T4[i + 2] = s2;
        g_sxw4[i + 3] = s3;  g_T4[i + 3] = s3;
    }
    cudaTriggerProgrammaticLaunchCompletion();
}

// ---------------------------------------------------------------------------
// 3) Edge scatter: single-wave grid-stride (1184 blocks), 4 edges per chunk,
//    int4 index loads, LDG.128 gather + RED.128 per edge. ~2.64 chunks/thread
//    give extra MLP; no wave transitions. Straight-line loop body — ptxas
//    front-batches the loads itself; manual pipelining regressed (round 13).
__global__ void __launch_bounds__(EDGE_THREADS, 8)
k_edge(const int* __restrict__ ei) {
    const unsigned gtid = blockIdx.x * EDGE_THREADS + threadIdx.x;
    const unsigned NCHUNK = N_EDGES / 4;       // 800,000 exact

    // First chunk's indices pre-sync (pure input).
    int4 r4 = make_int4(-1, -1, -1, -1);
    int4 c4 = make_int4(-1, -1, -1, -1);
    if (gtid < NCHUNK) {
        r4 = *reinterpret_cast<const int4*>(ei + gtid * 4);
        c4 = *reinterpret_cast<const int4*>(ei + N_EDGES + gtid * 4);
    }
    cudaGridDependencySynchronize();           // sxw4 / T4 ready

    for (unsigned c = gtid; c < NCHUNK; ) {
        // issue gathers + REDs for current chunk
        if ((unsigned)r4.x < N_NODES && (unsigned)c4.x < N_NODES)
            atomicAdd(&g_T4[c4.x], g_sxw4[r4.x]);
        if ((unsigned)r4.y < N_NODES && (unsigned)c4.y < N_NODES)
            atomicAdd(&g_T4[c4.y], g_sxw4[r4.y]);
        if ((unsigned)r4.z < N_NODES && (unsigned)c4.z < N_NODES)
            atomicAdd(&g_T4[c4.z], g_sxw4[r4.z]);
        if ((unsigned)r4.w < N_NODES && (unsigned)c4.w < N_NODES)
            atomicAdd(&g_T4[c4.w], g_sxw4[r4.w]);
        // fetch next chunk's indices (overlaps the REDs above)
        c += EDGE_TOTAL;
        if (c < NCHUNK) {
            r4 = *reinterpret_cast<const int4*>(ei + c * 4);
            c4 = *reinterpret_cast<const int4*>(ei + N_EDGES + c * 4);
        } else break;
    }
    cudaTriggerProgrammaticLaunchCompletion();
}

// ---------------------------------------------------------------------------
// 4) Epilogue, role-split over 2*N_NODES threads:
//    t < N:  compute h[t], store 3 floats;  t >= N: recompute h, store z float4.
__global__ void k_final(const float* __restrict__ b,
                        const float* __restrict__ Wout,
                        const float* __restrict__ bout,
                        float* __restrict__ out) {
    unsigned t = blockIdx.x * blockDim.x + threadIdx.x;
    bool zrole = (t >= N_NODES);
    unsigned i = zrole ? t - N_NODES : t;
    bool valid = (t < 2u * N_NODES);

    float b0 = __ldg(&b[0]), b1 = __ldg(&b[1]), b2 = __ldg(&b[2]);
    float w00 = 0, w01 = 0, w02 = 0, w03 = 0;
    float w10 = 0, w11 = 0, w12 = 0, w13 = 0;
    float w20 = 0, w21 = 0, w22 = 0, w23 = 0;
    float zb0 = 0, zb1 = 0, zb2 = 0, zb3 = 0;
    if (zrole) {
        w00 = __ldg(&Wout[0]);  w01 = __ldg(&Wout[1]);  w02 = __ldg(&Wout[2]);  w03 = __ldg(&Wout[3]);
        w10 = __ldg(&Wout[4]);  w11 = __ldg(&Wout[5]);  w12 = __ldg(&Wout[6]);  w13 = __ldg(&Wout[7]);
        w20 = __ldg(&Wout[8]);  w21 = __ldg(&Wout[9]);  w22 = __ldg(&Wout[10]); w23 = __ldg(&Wout[11]);
        zb0 = __ldg(&bout[0]);  zb1 = __ldg(&bout[1]);  zb2 = __ldg(&bout[2]);  zb3 = __ldg(&bout[3]);
    }

    cudaGridDependencySynchronize();   // T4 aggregation complete
    if (!valid) return;

    float dinv = g_dinv[i];
    float4 tv  = g_T4[i];
    float h0 = fmaxf(tv.x * dinv + b0, 0.0f);
    float h1 = fmaxf(tv.y * dinv + b1, 0.0f);
    float h2 = fmaxf(tv.z * dinv + b2, 0.0f);

    if (!zrole) {
        unsigned base = i * HID;
        out[base + 0] = h0;
        out[base + 1] = h1;
        out[base + 2] = h2;
    } else {
        float4 z;
        z.x = h0 * w00 + h1 * w10 + h2 * w20 + zb0;
        z.y = h0 * w01 + h1 * w11 + h2 * w21 + zb1;
        z.z = h0 * w02 + h1 * w12 + h2 * w22 + zb2;
        z.w = h0 * w03 + h1 * w13 + h2 * w23 + zb3;
        *reinterpret_cast<float4*>(out + (size_t)N_NODES * HID + (size_t)i * OUT_F) = z;
    }
}

// ---------------------------------------------------------------------------
static inline void launch_pdl(void* fn, dim3 grid, dim3 block, void** args) {
    cudaLaunchConfig_t cfg = {};
    cfg.gridDim = grid;
    cfg.blockDim = block;
    cfg.dynamicSmemBytes = 0;
    cfg.stream = 0;   // capturing (default) stream
    cudaLaunchAttribute attr[1];
    attr[0].id = cudaLaunchAttributeProgrammaticStreamSerialization;
    attr[0].val.programmaticStreamSerializationAllowed = 1;
    cfg.attrs = attr;
    cfg.numAttrs = 1;
    cudaLaunchKernelExC(&cfg, fn, args);
}

extern "C" void kernel_launch(void* const* d_in, const int* in_sizes, int n_in,
                              void* d_out, int out_size) {
    // Bind inputs by element count (robust to ordering):
    // x=12,800,000  edge_index=6,400,000  W=384  b=3  Wout=12  bout=4
    const float* x    = nullptr;
    const int*   ei   = nullptr;
    const float* W    = nullptr;
    const float* b    = nullptr;
    const float* Wout = nullptr;
    const float* bout = nullptr;
    for (int i = 0; i < n_in; i++) {
        switch (in_sizes[i]) {
            case 12800000: x    = (const float*)d_in[i]; break;
            case 6400000:  ei   = (const int*)  d_in[i]; break;
            case 384:      W    = (const float*)d_in[i]; break;
            case 3:        b    = (const float*)d_in[i]; break;
            case 12:       Wout = (const float*)d_in[i]; break;
            case 4:        bout = (const float*)d_in[i]; break;
            default: break;
        }
    }

    float* out = (float*)d_out;
    const int T = 256;
    const int* col = ei + N_EDGES;

    {
        void* args[] = { (void*)&col, (void*)&x, (void*)&W };
        launch_pdl((void*)k_deg_gemv, dim3(FUSED_BLOCKS), dim3(T), args);
    }
    {
        void* args[] = { };
        cudaLaunchConfig_t cfg = {};
        cfg.gridDim = dim3((N_NODES / 4 + T - 1) / T);
        cfg.blockDim = dim3(T);
        cfg.stream = 0;
        cudaLaunchAttribute attr[1];
        attr[0].id = cudaLaunchAttributeProgrammaticStreamSerialization;
        attr[0].val.programmaticStreamSerializationAllowed = 1;
        cfg.attrs = attr;
        cfg.numAttrs = 1;
        cudaLaunchKernelExC(&cfg, (void*)k_scale, args);
    }
    {
        void* args[] = { (void*)&ei };
        launch_pdl((void*)k_edge, dim3(EDGE_BLOCKS), dim3(EDGE_THREADS), args);
    }
    {
        void* args[] = { (void*)&b, (void*)&Wout, (void*)&bout, (void*)&out };
        launch_pdl((void*)k_final, dim3((2 * N_NODES + T - 1) / T), dim3(T), args);
    }
}